// round 9
// baseline (speedup 1.0000x reference)
#include <cuda_runtime.h>
#include <cuda_bf16.h>
#include <math_constants.h>

// MultiLocalCosineLinear, pair-sorted compute with register-resident weights:
//   K0: zero hist
//   K1: warp/row top-2 -> (a,b,pair); rank = atomicAdd(hist[pair])
//   K2: exclusive scan of hist -> g_start
//   K3: scatter row -> sorted slot (start+rank), no atomics
//   K4: warp per 16 consecutive sorted slots; weight pair (48 regs) reloaded
//       only when pair changes inside the window (~1-2x per warp).
//   out (float32): [0,B) preds, [B,3B) logits row-major (B,2)

#define NROWS   65536
#define DDIM    768
#define NCLS    100
#define NPAIRS  4950
#define F4L     6                  // 768/4/32
#define CHUNK   16                 // sorted slots per warp (65536/16=4096 warps)

__device__ int g_hist[NPAIRS];
__device__ int g_start[NPAIRS + 1];
__device__ int g_rowinfo[NROWS];   // pair | rank<<13
__device__ int g_ab[NROWS];        // a | b<<16
__device__ int g_srow[NROWS];      // sorted: row id
__device__ int g_sinfo[NROWS];     // sorted: pair | a<<13 | b<<20

__device__ __forceinline__ float warp_sum(float v) {
    #pragma unroll
    for (int o = 16; o; o >>= 1) v += __shfl_xor_sync(0xffffffffu, v, o);
    return v;
}
__device__ __forceinline__ float ldcs_f(const float* p) {
    float v; asm volatile("ld.global.cs.f32 %0, [%1];" : "=f"(v) : "l"(p)); return v;
}
__device__ __forceinline__ float4 ldcs_f4(const float4* p) {
    float4 v;
    asm volatile("ld.global.cs.v4.f32 {%0,%1,%2,%3}, [%4];"
                 : "=f"(v.x), "=f"(v.y), "=f"(v.z), "=f"(v.w) : "l"(p));
    return v;
}

// ---------------- K0 ----------------
__global__ void k_zero() {
    int i = blockIdx.x * blockDim.x + threadIdx.x;
    if (i < NPAIRS) g_hist[i] = 0;
}

// ---------------- K1: top-2 + rank ----------------
__global__ __launch_bounds__(256, 8)
void k_top2(const float* __restrict__ first_out) {
    const int row  = blockIdx.x * 8 + (threadIdx.x >> 5);
    const int lane = threadIdx.x & 31;
    if (row >= NROWS) return;

    const float* fo = first_out + (size_t)row * NCLS;
    float v1 = -CUDART_INF_F, v2 = -CUDART_INF_F;
    int   i1 = NCLS,          i2 = NCLS;
    #pragma unroll
    for (int t = 0; t < 4; ++t) {
        int c = lane + 32 * t;
        float v = (c < NCLS) ? ldcs_f(fo + c) : -CUDART_INF_F;
        if (v > v1) { v2 = v1; i2 = i1; v1 = v; i1 = c; }
        else if (v > v2) { v2 = v; i2 = c; }
        // increasing index: equal values never displace an earlier index
    }
    #pragma unroll
    for (int off = 16; off; off >>= 1) {
        float w1 = __shfl_xor_sync(0xffffffffu, v1, off);
        int   j1 = __shfl_xor_sync(0xffffffffu, i1, off);
        float w2 = __shfl_xor_sync(0xffffffffu, v2, off);
        int   j2 = __shfl_xor_sync(0xffffffffu, i2, off);
        bool w1_best = (w1 > v1) || (w1 == v1 && j1 < i1);
        if (w1_best) {
            bool v1_second = (v1 > w2) || (v1 == w2 && i1 < j2);
            v2 = v1_second ? v1 : w2;
            i2 = v1_second ? i1 : j2;
            v1 = w1; i1 = j1;
        } else {
            bool w1_second = (w1 > v2) || (w1 == v2 && j1 < i2);
            if (w1_second) { v2 = w1; i2 = j1; }
        }
    }
    if (lane == 0) {
        const int a = min(i1, i2);
        const int b = max(i1, i2);
        const int pair = b * (b - 1) / 2 + a;      // < 4950 -> 13 bits
        const int rank = atomicAdd(&g_hist[pair], 1);
        g_ab[row] = a | (b << 16);
        g_rowinfo[row] = pair | (rank << 13);
    }
}

// ---------------- K2: exclusive scan ----------------
__global__ void k_scan() {
    __shared__ int partial[1024];
    const int tid = threadIdx.x;               // 1024 threads
    const int PER = 5;                         // 5120 >= NPAIRS
    int base = tid * PER;
    int loc[PER];
    int sum = 0;
    #pragma unroll
    for (int i = 0; i < PER; ++i) {
        int idx = base + i;
        int v = (idx < NPAIRS) ? g_hist[idx] : 0;
        loc[i] = sum; sum += v;
    }
    partial[tid] = sum;
    __syncthreads();
    for (int off = 1; off < 1024; off <<= 1) {
        int t = (tid >= off) ? partial[tid - off] : 0;
        __syncthreads();
        partial[tid] += t;
        __syncthreads();
    }
    int chunk_start = (tid > 0) ? partial[tid - 1] : 0;
    #pragma unroll
    for (int i = 0; i < PER; ++i) {
        int idx = base + i;
        if (idx < NPAIRS) g_start[idx] = chunk_start + loc[i];
    }
    if (tid == 1023) g_start[NPAIRS] = partial[1023];
}

// ---------------- K3: scatter (plain stores) ----------------
__global__ void k_scatter() {
    int row = blockIdx.x * blockDim.x + threadIdx.x;
    if (row >= NROWS) return;
    int v = g_rowinfo[row];
    int pair = v & 8191;
    int rank = v >> 13;
    int pos = g_start[pair] + rank;
    int ab = g_ab[row];
    g_srow[pos]  = row;
    g_sinfo[pos] = pair | ((ab & 0xffff) << 13) | ((ab >> 16) << 20);
}

// ---------------- K4: warp per 16 sorted slots ----------------
__global__ __launch_bounds__(256, 2)
void k_compute(const float* __restrict__ x,
               const float* __restrict__ weights,
               const float* __restrict__ sigma,
               float* __restrict__ out)
{
    const int warp = blockIdx.x * 8 + (threadIdx.x >> 5);
    const int lane = threadIdx.x & 31;
    const int p0 = warp * CHUNK;
    if (p0 >= NROWS) return;

    int cur_pair = -1;
    float4 w0[F4L], w1[F4L];
    float sc0 = 0.f, sc1 = 0.f;

    #pragma unroll 1
    for (int i = 0; i < CHUNK; ++i) {
        const int pos  = p0 + i;
        const int info = g_sinfo[pos];       // broadcast (all lanes same addr)
        const int pair = info & 8191;

        if (pair != cur_pair) {              // warp-uniform branch
            cur_pair = pair;
            const float4* w4 = (const float4*)(weights + (size_t)pair * 2 * DDIM);
            float wss0 = 0.f, wss1 = 0.f;
            #pragma unroll
            for (int j = 0; j < F4L; ++j) {
                w0[j] = __ldg(w4 + lane + 32 * j);
                w1[j] = __ldg(w4 + 192 + lane + 32 * j);
            }
            #pragma unroll
            for (int j = 0; j < F4L; ++j) {
                float4 a = w0[j], b = w1[j];
                wss0 = fmaf(a.x, a.x, fmaf(a.y, a.y, fmaf(a.z, a.z, fmaf(a.w, a.w, wss0))));
                wss1 = fmaf(b.x, b.x, fmaf(b.y, b.y, fmaf(b.z, b.z, fmaf(b.w, b.w, wss1))));
            }
            wss0 = warp_sum(wss0);
            wss1 = warp_sum(wss1);
            const float sg = __ldg(sigma + pair);
            sc0 = sg / fmaxf(sqrtf(wss0), 1e-12f);
            sc1 = sg / fmaxf(sqrtf(wss1), 1e-12f);
        }

        const int row = g_srow[pos];
        const float4* xr = (const float4*)(x + (size_t)row * DDIM);
        float xss = 0.f, d0 = 0.f, d1 = 0.f;
        #pragma unroll
        for (int j = 0; j < F4L; ++j) {
            float4 v = ldcs_f4(xr + lane + 32 * j);
            float4 a = w0[j], b = w1[j];
            xss = fmaf(v.x, v.x, fmaf(v.y, v.y, fmaf(v.z, v.z, fmaf(v.w, v.w, xss))));
            d0  = fmaf(a.x, v.x, fmaf(a.y, v.y, fmaf(a.z, v.z, fmaf(a.w, v.w, d0))));
            d1  = fmaf(b.x, v.x, fmaf(b.y, v.y, fmaf(b.z, v.z, fmaf(b.w, v.w, d1))));
        }
        xss = warp_sum(xss);
        d0  = warp_sum(d0);
        d1  = warp_sum(d1);

        if (lane == 0) {
            const float xinv = 1.0f / fmaxf(sqrtf(xss), 1e-12f);
            const float l0 = sc0 * d0 * xinv;
            const float l1 = sc1 * d1 * xinv;
            const int a = (info >> 13) & 127;
            const int b = (info >> 20) & 127;
            out[row] = (float)((l1 > l0) ? b : a);    // argmax, first on tie
            *(float2*)(out + (size_t)NROWS + 2 * (size_t)row) = make_float2(l0, l1);
        }
    }
}

extern "C" void kernel_launch(void* const* d_in, const int* in_sizes, int n_in,
                              void* d_out, int out_size) {
    const float* x        = (const float*)d_in[0];
    const float* first_o  = (const float*)d_in[1];
    const float* weights  = (const float*)d_in[2];
    const float* sigma    = (const float*)d_in[3];
    float* out = (float*)d_out;

    k_zero<<<(NPAIRS + 255) / 256, 256>>>();
    k_top2<<<NROWS / 8, 256>>>(first_o);
    k_scan<<<1, 1024>>>();
    k_scatter<<<NROWS / 256, 256>>>();
    k_compute<<<NROWS / CHUNK / 8, 256>>>(x, weights, sigma, out);
}

// round 10
// speedup vs baseline: 1.1702x; 1.1702x over previous
#include <cuda_runtime.h>
#include <cuda_bf16.h>
#include <math_constants.h>

// MultiLocalCosineLinear, 2-kernel split (R9):
//   K1: warp per 4 rows; one float4 load per row (25 lanes), staged -> MLP 4;
//       top-2 butterfly per row -> g_info[row] = pair | a<<13 | b<<20
//   K2: warp per row, <=64 regs (4 CTAs/SM): pair known up front, 18 loads
//       (6 x-float4 + 12 w-float4) in flight before any reduction.
//   out (float32): [0,B) preds, [B,3B) logits row-major (B,2)

#define NROWS   65536
#define DDIM    768
#define NCLS    100
#define F4L     6                 // 768/4/32

__device__ int g_info[NROWS];     // pair | a<<13 | b<<20

__device__ __forceinline__ float warp_sum(float v) {
    #pragma unroll
    for (int o = 16; o; o >>= 1) v += __shfl_xor_sync(0xffffffffu, v, o);
    return v;
}
__device__ __forceinline__ float4 ldcs_f4(const float4* p) {
    float4 v;
    asm volatile("ld.global.cs.v4.f32 {%0,%1,%2,%3}, [%4];"
                 : "=f"(v.x), "=f"(v.y), "=f"(v.z), "=f"(v.w) : "l"(p));
    return v;
}

// ---------------- K1: top-2, 4 rows per warp ----------------
__global__ __launch_bounds__(256, 4)
void k_top2(const float* __restrict__ first_out) {
    const int warp = blockIdx.x * 8 + (threadIdx.x >> 5);
    const int lane = threadIdx.x & 31;
    const int r0   = warp * 4;
    if (r0 >= NROWS) return;

    // stage all 4 rows' loads first (MLP=4); 100 floats = 25 float4 per row
    float4 fv[4];
    #pragma unroll
    for (int t = 0; t < 4; ++t) {
        if (lane < 25) {
            const float4* fo4 = (const float4*)(first_out + (size_t)(r0 + t) * NCLS);
            fv[t] = ldcs_f4(fo4 + lane);
        } else {
            fv[t] = make_float4(-CUDART_INF_F, -CUDART_INF_F, -CUDART_INF_F, -CUDART_INF_F);
        }
    }

    #pragma unroll
    for (int t = 0; t < 4; ++t) {
        // in-lane top2 over 4 consecutive values, c = 4*lane + q (increasing)
        float vals[4] = {fv[t].x, fv[t].y, fv[t].z, fv[t].w};
        float v1 = -CUDART_INF_F, v2 = -CUDART_INF_F;
        int   i1 = 1023,          i2 = 1023;
        #pragma unroll
        for (int q = 0; q < 4; ++q) {
            float v = vals[q];
            int   c = 4 * lane + q;
            if (v > v1) { v2 = v1; i2 = i1; v1 = v; i1 = c; }
            else if (v > v2) { v2 = v; i2 = c; }
            // increasing index: equal values never displace an earlier index
        }
        // butterfly merge, ties -> lower index (jax top_k semantics)
        #pragma unroll
        for (int off = 16; off; off >>= 1) {
            float w1 = __shfl_xor_sync(0xffffffffu, v1, off);
            int   j1 = __shfl_xor_sync(0xffffffffu, i1, off);
            float w2 = __shfl_xor_sync(0xffffffffu, v2, off);
            int   j2 = __shfl_xor_sync(0xffffffffu, i2, off);
            bool w1_best = (w1 > v1) || (w1 == v1 && j1 < i1);
            if (w1_best) {
                bool v1_second = (v1 > w2) || (v1 == w2 && i1 < j2);
                v2 = v1_second ? v1 : w2;
                i2 = v1_second ? i1 : j2;
                v1 = w1; i1 = j1;
            } else {
                bool w1_second = (w1 > v2) || (w1 == v2 && j1 < i2);
                if (w1_second) { v2 = w1; i2 = j1; }
            }
        }
        if (lane == 0) {
            const int a = min(i1, i2);
            const int b = max(i1, i2);
            const int pair = b * (b - 1) / 2 + a;     // < 4950, 13 bits
            g_info[r0 + t] = pair | (a << 13) | (b << 20);
        }
    }
}

// ---------------- K2: warp per row, max-MLP compute ----------------
__global__ __launch_bounds__(256, 4)
void k_compute(const float* __restrict__ x,
               const float* __restrict__ weights,
               const float* __restrict__ sigma,
               float* __restrict__ out)
{
    const int row  = blockIdx.x * 8 + (threadIdx.x >> 5);
    const int lane = threadIdx.x & 31;
    if (row >= NROWS) return;

    const int info = g_info[row];          // broadcast, L2-resident (written by K1)
    const int pair = info & 8191;

    const float4* x4 = (const float4*)(x + (size_t)row * DDIM);
    const float4* w4 = (const float4*)(weights + (size_t)pair * 2 * DDIM);

    // x row -> registers (streaming), issued before any dependent math
    float4 xf[F4L];
    #pragma unroll
    for (int j = 0; j < F4L; ++j) xf[j] = ldcs_f4(x4 + lane + 32 * j);

    // both weight rows streamed in one fused loop: 12 more loads in flight
    float xss = 0.f, d0 = 0.f, s0 = 0.f, d1 = 0.f, s1 = 0.f;
    #pragma unroll
    for (int j = 0; j < F4L; ++j) {
        const int idx = lane + 32 * j;
        float4 w0 = __ldg(w4 + idx);
        float4 w1 = __ldg(w4 + 192 + idx);
        float4 a  = xf[j];
        xss = fmaf(a.x, a.x, fmaf(a.y, a.y, fmaf(a.z, a.z, fmaf(a.w, a.w, xss))));
        d0  = fmaf(w0.x, a.x, fmaf(w0.y, a.y, fmaf(w0.z, a.z, fmaf(w0.w, a.w, d0))));
        s0  = fmaf(w0.x, w0.x, fmaf(w0.y, w0.y, fmaf(w0.z, w0.z, fmaf(w0.w, w0.w, s0))));
        d1  = fmaf(w1.x, a.x, fmaf(w1.y, a.y, fmaf(w1.z, a.z, fmaf(w1.w, a.w, d1))));
        s1  = fmaf(w1.x, w1.x, fmaf(w1.y, w1.y, fmaf(w1.z, w1.z, fmaf(w1.w, w1.w, s1))));
    }

    xss = warp_sum(xss);
    d0  = warp_sum(d0);
    s0  = warp_sum(s0);
    d1  = warp_sum(d1);
    s1  = warp_sum(s1);

    if (lane == 0) {
        const float sg   = __ldg(sigma + pair);
        const float xinv = 1.0f / fmaxf(sqrtf(xss), 1e-12f);
        const float l0 = sg * d0 * xinv / fmaxf(sqrtf(s0), 1e-12f);
        const float l1 = sg * d1 * xinv / fmaxf(sqrtf(s1), 1e-12f);
        const int a = (info >> 13) & 127;
        const int b = (info >> 20) & 127;
        out[row] = (float)((l1 > l0) ? b : a);       // argmax, first on tie
        *(float2*)(out + (size_t)NROWS + 2 * (size_t)row) = make_float2(l0, l1);
    }
}

extern "C" void kernel_launch(void* const* d_in, const int* in_sizes, int n_in,
                              void* d_out, int out_size) {
    const float* x        = (const float*)d_in[0];
    const float* first_o  = (const float*)d_in[1];
    const float* weights  = (const float*)d_in[2];
    const float* sigma    = (const float*)d_in[3];
    float* out = (float*)d_out;

    k_top2<<<NROWS / 32, 256>>>(first_o);           // 4 rows/warp, 8 warps/block
    k_compute<<<NROWS / 8, 256>>>(x, weights, sigma, out);
}

// round 11
// speedup vs baseline: 1.3103x; 1.1197x over previous
#include <cuda_runtime.h>
#include <cuda_bf16.h>
#include <math_constants.h>

// MultiLocalCosineLinear, 2-kernel split (R10):
//   K1: warp per 4 rows; one float4 load per row (25 lanes); top-2 via
//       sortable-int keys + __reduce_{max,min}_sync (4 redux per row instead
//       of a 20-shuffle butterfly). -> g_info[row] = pair | a<<13 | b<<20
//   K2: warp per row (unchanged R9 winner): pair known up front, 18 loads
//       (6 x-float4 + 12 w-float4) in flight before any reduction.
//   out (float32): [0,B) preds, [B,3B) logits row-major (B,2)

#define NROWS   65536
#define DDIM    768
#define NCLS    100
#define F4L     6                 // 768/4/32

__device__ int g_info[NROWS];     // pair | a<<13 | b<<20

__device__ __forceinline__ float warp_sum(float v) {
    #pragma unroll
    for (int o = 16; o; o >>= 1) v += __shfl_xor_sync(0xffffffffu, v, o);
    return v;
}
__device__ __forceinline__ float4 ldcs_f4(const float4* p) {
    float4 v;
    asm volatile("ld.global.cs.v4.f32 {%0,%1,%2,%3}, [%4];"
                 : "=f"(v.x), "=f"(v.y), "=f"(v.z), "=f"(v.w) : "l"(p));
    return v;
}
// order-preserving float -> signed int key (finite inputs; -inf maps lowest)
__device__ __forceinline__ int fkey(float f) {
    int i = __float_as_int(f);
    return (i >= 0) ? i : (i ^ 0x7fffffff);
}

// ---------------- K1: top-2, 4 rows per warp, redux-based ----------------
__global__ __launch_bounds__(256, 4)
void k_top2(const float* __restrict__ first_out) {
    const int warp = blockIdx.x * 8 + (threadIdx.x >> 5);
    const int lane = threadIdx.x & 31;
    const int r0   = warp * 4;
    if (r0 >= NROWS) return;

    // stage all 4 rows' loads first (MLP=4); 100 floats = 25 float4 per row
    float4 fv[4];
    #pragma unroll
    for (int t = 0; t < 4; ++t) {
        if (lane < 25) {
            const float4* fo4 = (const float4*)(first_out + (size_t)(r0 + t) * NCLS);
            fv[t] = ldcs_f4(fo4 + lane);
        } else {
            fv[t] = make_float4(-CUDART_INF_F, -CUDART_INF_F, -CUDART_INF_F, -CUDART_INF_F);
        }
    }

    #pragma unroll
    for (int t = 0; t < 4; ++t) {
        // per-lane keys; c = 4*lane + q (increasing within lane)
        const int k0 = fkey(fv[t].x), k1 = fkey(fv[t].y);
        const int k2 = fkey(fv[t].z), k3 = fkey(fv[t].w);
        const int c0 = 4 * lane;

        // per-lane top2 (strict >, increasing index => ties keep lower idx)
        int bk1 = k0, bi1 = c0;
        int bk2 = 0x80000000, bi2 = 0x7fffffff;
        if (k1 > bk1) { bk2 = bk1; bi2 = bi1; bk1 = k1; bi1 = c0 + 1; }
        else if (k1 > bk2) { bk2 = k1; bi2 = c0 + 1; }
        if (k2 > bk1) { bk2 = bk1; bi2 = bi1; bk1 = k2; bi1 = c0 + 2; }
        else if (k2 > bk2) { bk2 = k2; bi2 = c0 + 2; }
        if (k3 > bk1) { bk2 = bk1; bi2 = bi1; bk1 = k3; bi1 = c0 + 3; }
        else if (k3 > bk2) { bk2 = k3; bi2 = c0 + 3; }

        // warp top-1: max key, then min index among key==max (jax tie-break)
        const int K1 = __reduce_max_sync(0xffffffffu, bk1);
        const int I1 = __reduce_min_sync(0xffffffffu,
                            (bk1 == K1) ? bi1 : 0x7fffffff);

        // warp top-2: winner lane substitutes its second-best
        const bool won = (bi1 == I1);
        const int sk = won ? bk2 : bk1;
        const int si = won ? bi2 : bi1;
        const int K2 = __reduce_max_sync(0xffffffffu, sk);
        const int I2 = __reduce_min_sync(0xffffffffu,
                            (sk == K2) ? si : 0x7fffffff);

        if (lane == 0) {
            const int a = min(I1, I2);
            const int b = max(I1, I2);
            const int pair = b * (b - 1) / 2 + a;     // < 4950, 13 bits
            g_info[r0 + t] = pair | (a << 13) | (b << 20);
        }
    }
}

// ---------------- K2: warp per row, max-MLP compute (R9 winner) ----------------
__global__ __launch_bounds__(256, 4)
void k_compute(const float* __restrict__ x,
               const float* __restrict__ weights,
               const float* __restrict__ sigma,
               float* __restrict__ out)
{
    const int row  = blockIdx.x * 8 + (threadIdx.x >> 5);
    const int lane = threadIdx.x & 31;
    if (row >= NROWS) return;

    const int info = g_info[row];          // broadcast, L2-resident
    const int pair = info & 8191;

    const float4* x4 = (const float4*)(x + (size_t)row * DDIM);
    const float4* w4 = (const float4*)(weights + (size_t)pair * 2 * DDIM);

    // x row -> registers (streaming), issued before any dependent math
    float4 xf[F4L];
    #pragma unroll
    for (int j = 0; j < F4L; ++j) xf[j] = ldcs_f4(x4 + lane + 32 * j);

    // both weight rows streamed in one fused loop: 12 more loads in flight
    float xss = 0.f, d0 = 0.f, s0 = 0.f, d1 = 0.f, s1 = 0.f;
    #pragma unroll
    for (int j = 0; j < F4L; ++j) {
        const int idx = lane + 32 * j;
        float4 w0 = __ldg(w4 + idx);
        float4 w1 = __ldg(w4 + 192 + idx);
        float4 a  = xf[j];
        xss = fmaf(a.x, a.x, fmaf(a.y, a.y, fmaf(a.z, a.z, fmaf(a.w, a.w, xss))));
        d0  = fmaf(w0.x, a.x, fmaf(w0.y, a.y, fmaf(w0.z, a.z, fmaf(w0.w, a.w, d0))));
        s0  = fmaf(w0.x, w0.x, fmaf(w0.y, w0.y, fmaf(w0.z, w0.z, fmaf(w0.w, w0.w, s0))));
        d1  = fmaf(w1.x, a.x, fmaf(w1.y, a.y, fmaf(w1.z, a.z, fmaf(w1.w, a.w, d1))));
        s1  = fmaf(w1.x, w1.x, fmaf(w1.y, w1.y, fmaf(w1.z, w1.z, fmaf(w1.w, w1.w, s1))));
    }

    xss = warp_sum(xss);
    d0  = warp_sum(d0);
    s0  = warp_sum(s0);
    d1  = warp_sum(d1);
    s1  = warp_sum(s1);

    if (lane == 0) {
        const float sg   = __ldg(sigma + pair);
        const float xinv = 1.0f / fmaxf(sqrtf(xss), 1e-12f);
        const float l0 = sg * d0 * xinv / fmaxf(sqrtf(s0), 1e-12f);
        const float l1 = sg * d1 * xinv / fmaxf(sqrtf(s1), 1e-12f);
        const int a = (info >> 13) & 127;
        const int b = (info >> 20) & 127;
        out[row] = (float)((l1 > l0) ? b : a);       // argmax, first on tie
        *(float2*)(out + (size_t)NROWS + 2 * (size_t)row) = make_float2(l0, l1);
    }
}

extern "C" void kernel_launch(void* const* d_in, const int* in_sizes, int n_in,
                              void* d_out, int out_size) {
    const float* x        = (const float*)d_in[0];
    const float* first_o  = (const float*)d_in[1];
    const float* weights  = (const float*)d_in[2];
    const float* sigma    = (const float*)d_in[3];
    float* out = (float*)d_out;

    k_top2<<<NROWS / 32, 256>>>(first_o);           // 4 rows/warp
    k_compute<<<NROWS / 8, 256>>>(x, weights, sigma, out);
}

// round 12
// speedup vs baseline: 1.3158x; 1.0042x over previous
#include <cuda_runtime.h>
#include <cuda_bf16.h>
#include <math_constants.h>

// MultiLocalCosineLinear, 2-kernel split (R10):
//   K1: warp per 4 rows; one float4 load per row (25 lanes); top-2 via
//       sortable-int keys + __reduce_{max,min}_sync (4 redux per row instead
//       of a 20-shuffle butterfly). -> g_info[row] = pair | a<<13 | b<<20
//   K2: warp per row (unchanged R9 winner): pair known up front, 18 loads
//       (6 x-float4 + 12 w-float4) in flight before any reduction.
//   out (float32): [0,B) preds, [B,3B) logits row-major (B,2)

#define NROWS   65536
#define DDIM    768
#define NCLS    100
#define F4L     6                 // 768/4/32

__device__ int g_info[NROWS];     // pair | a<<13 | b<<20

__device__ __forceinline__ float warp_sum(float v) {
    #pragma unroll
    for (int o = 16; o; o >>= 1) v += __shfl_xor_sync(0xffffffffu, v, o);
    return v;
}
__device__ __forceinline__ float4 ldcs_f4(const float4* p) {
    float4 v;
    asm volatile("ld.global.cs.v4.f32 {%0,%1,%2,%3}, [%4];"
                 : "=f"(v.x), "=f"(v.y), "=f"(v.z), "=f"(v.w) : "l"(p));
    return v;
}
// order-preserving float -> signed int key (finite inputs; -inf maps lowest)
__device__ __forceinline__ int fkey(float f) {
    int i = __float_as_int(f);
    return (i >= 0) ? i : (i ^ 0x7fffffff);
}

// ---------------- K1: top-2, 4 rows per warp, redux-based ----------------
__global__ __launch_bounds__(256, 4)
void k_top2(const float* __restrict__ first_out) {
    const int warp = blockIdx.x * 8 + (threadIdx.x >> 5);
    const int lane = threadIdx.x & 31;
    const int r0   = warp * 4;
    if (r0 >= NROWS) return;

    // stage all 4 rows' loads first (MLP=4); 100 floats = 25 float4 per row
    float4 fv[4];
    #pragma unroll
    for (int t = 0; t < 4; ++t) {
        if (lane < 25) {
            const float4* fo4 = (const float4*)(first_out + (size_t)(r0 + t) * NCLS);
            fv[t] = ldcs_f4(fo4 + lane);
        } else {
            fv[t] = make_float4(-CUDART_INF_F, -CUDART_INF_F, -CUDART_INF_F, -CUDART_INF_F);
        }
    }

    #pragma unroll
    for (int t = 0; t < 4; ++t) {
        // per-lane keys; c = 4*lane + q (increasing within lane)
        const int k0 = fkey(fv[t].x), k1 = fkey(fv[t].y);
        const int k2 = fkey(fv[t].z), k3 = fkey(fv[t].w);
        const int c0 = 4 * lane;

        // per-lane top2 (strict >, increasing index => ties keep lower idx)
        int bk1 = k0, bi1 = c0;
        int bk2 = 0x80000000, bi2 = 0x7fffffff;
        if (k1 > bk1) { bk2 = bk1; bi2 = bi1; bk1 = k1; bi1 = c0 + 1; }
        else if (k1 > bk2) { bk2 = k1; bi2 = c0 + 1; }
        if (k2 > bk1) { bk2 = bk1; bi2 = bi1; bk1 = k2; bi1 = c0 + 2; }
        else if (k2 > bk2) { bk2 = k2; bi2 = c0 + 2; }
        if (k3 > bk1) { bk2 = bk1; bi2 = bi1; bk1 = k3; bi1 = c0 + 3; }
        else if (k3 > bk2) { bk2 = k3; bi2 = c0 + 3; }

        // warp top-1: max key, then min index among key==max (jax tie-break)
        const int K1 = __reduce_max_sync(0xffffffffu, bk1);
        const int I1 = __reduce_min_sync(0xffffffffu,
                            (bk1 == K1) ? bi1 : 0x7fffffff);

        // warp top-2: winner lane substitutes its second-best
        const bool won = (bi1 == I1);
        const int sk = won ? bk2 : bk1;
        const int si = won ? bi2 : bi1;
        const int K2 = __reduce_max_sync(0xffffffffu, sk);
        const int I2 = __reduce_min_sync(0xffffffffu,
                            (sk == K2) ? si : 0x7fffffff);

        if (lane == 0) {
            const int a = min(I1, I2);
            const int b = max(I1, I2);
            const int pair = b * (b - 1) / 2 + a;     // < 4950, 13 bits
            g_info[r0 + t] = pair | (a << 13) | (b << 20);
        }
    }
}

// ---------------- K2: warp per row, max-MLP compute (R9 winner) ----------------
__global__ __launch_bounds__(256, 4)
void k_compute(const float* __restrict__ x,
               const float* __restrict__ weights,
               const float* __restrict__ sigma,
               float* __restrict__ out)
{
    const int row  = blockIdx.x * 8 + (threadIdx.x >> 5);
    const int lane = threadIdx.x & 31;
    if (row >= NROWS) return;

    const int info = g_info[row];          // broadcast, L2-resident
    const int pair = info & 8191;

    const float4* x4 = (const float4*)(x + (size_t)row * DDIM);
    const float4* w4 = (const float4*)(weights + (size_t)pair * 2 * DDIM);

    // x row -> registers (streaming), issued before any dependent math
    float4 xf[F4L];
    #pragma unroll
    for (int j = 0; j < F4L; ++j) xf[j] = ldcs_f4(x4 + lane + 32 * j);

    // both weight rows streamed in one fused loop: 12 more loads in flight
    float xss = 0.f, d0 = 0.f, s0 = 0.f, d1 = 0.f, s1 = 0.f;
    #pragma unroll
    for (int j = 0; j < F4L; ++j) {
        const int idx = lane + 32 * j;
        float4 w0 = __ldg(w4 + idx);
        float4 w1 = __ldg(w4 + 192 + idx);
        float4 a  = xf[j];
        xss = fmaf(a.x, a.x, fmaf(a.y, a.y, fmaf(a.z, a.z, fmaf(a.w, a.w, xss))));
        d0  = fmaf(w0.x, a.x, fmaf(w0.y, a.y, fmaf(w0.z, a.z, fmaf(w0.w, a.w, d0))));
        s0  = fmaf(w0.x, w0.x, fmaf(w0.y, w0.y, fmaf(w0.z, w0.z, fmaf(w0.w, w0.w, s0))));
        d1  = fmaf(w1.x, a.x, fmaf(w1.y, a.y, fmaf(w1.z, a.z, fmaf(w1.w, a.w, d1))));
        s1  = fmaf(w1.x, w1.x, fmaf(w1.y, w1.y, fmaf(w1.z, w1.z, fmaf(w1.w, w1.w, s1))));
    }

    xss = warp_sum(xss);
    d0  = warp_sum(d0);
    s0  = warp_sum(s0);
    d1  = warp_sum(d1);
    s1  = warp_sum(s1);

    if (lane == 0) {
        const float sg   = __ldg(sigma + pair);
        const float xinv = 1.0f / fmaxf(sqrtf(xss), 1e-12f);
        const float l0 = sg * d0 * xinv / fmaxf(sqrtf(s0), 1e-12f);
        const float l1 = sg * d1 * xinv / fmaxf(sqrtf(s1), 1e-12f);
        const int a = (info >> 13) & 127;
        const int b = (info >> 20) & 127;
        out[row] = (float)((l1 > l0) ? b : a);       // argmax, first on tie
        *(float2*)(out + (size_t)NROWS + 2 * (size_t)row) = make_float2(l0, l1);
    }
}

extern "C" void kernel_launch(void* const* d_in, const int* in_sizes, int n_in,
                              void* d_out, int out_size) {
    const float* x        = (const float*)d_in[0];
    const float* first_o  = (const float*)d_in[1];
    const float* weights  = (const float*)d_in[2];
    const float* sigma    = (const float*)d_in[3];
    float* out = (float*)d_out;

    k_top2<<<NROWS / 32, 256>>>(first_o);           // 4 rows/warp
    k_compute<<<NROWS / 8, 256>>>(x, weights, sigma, out);
}

// round 13
// speedup vs baseline: 1.3547x; 1.0296x over previous
#include <cuda_runtime.h>
#include <cuda_bf16.h>
#include <math_constants.h>

// MultiLocalCosineLinear, fused single kernel (R12):
//   warp per row:
//     1) issue first_out row load (25 lanes x float4, .cs)  [head of chain]
//     2) issue all 6 x float4 loads (.cs)                   [off-chain MLP]
//     3) top-2 via sortable-int keys + __reduce_{max,min}_sync
//     4) stream both weight rows (12 float4, default caching -> L2-resident),
//        5 fused FMA accumulators (xss, d0, s0, d1, s1)
//   out (float32): [0,B) preds, [B,3B) logits row-major (B,2)

#define NROWS   65536
#define DDIM    768
#define NCLS    100
#define F4L     6                 // 768/4/32

__device__ __forceinline__ float warp_sum(float v) {
    #pragma unroll
    for (int o = 16; o; o >>= 1) v += __shfl_xor_sync(0xffffffffu, v, o);
    return v;
}
__device__ __forceinline__ float4 ldcs_f4(const float4* p) {
    float4 v;
    asm volatile("ld.global.cs.v4.f32 {%0,%1,%2,%3}, [%4];"
                 : "=f"(v.x), "=f"(v.y), "=f"(v.z), "=f"(v.w) : "l"(p));
    return v;
}
// order-preserving float -> signed int key (-inf maps below all finite)
__device__ __forceinline__ int fkey(float f) {
    int i = __float_as_int(f);
    return (i >= 0) ? i : (i ^ 0x7fffffff);
}

__global__ __launch_bounds__(256, 4)
void mlcl_fused(const float* __restrict__ x,
                const float* __restrict__ first_out,
                const float* __restrict__ weights,
                const float* __restrict__ sigma,
                float* __restrict__ out)
{
    const int row  = blockIdx.x * 8 + (threadIdx.x >> 5);
    const int lane = threadIdx.x & 31;
    if (row >= NROWS) return;

    // 1) first_out row: one float4 per lane (25 active lanes) — chain head
    float4 fv;
    if (lane < 25) {
        const float4* fo4 = (const float4*)(first_out + (size_t)row * NCLS);
        fv = ldcs_f4(fo4 + lane);
    } else {
        fv = make_float4(-CUDART_INF_F, -CUDART_INF_F, -CUDART_INF_F, -CUDART_INF_F);
    }

    // 2) x row -> registers (streaming); independent of the top-2 chain
    const float4* x4 = (const float4*)(x + (size_t)row * DDIM);
    float4 xf[F4L];
    #pragma unroll
    for (int j = 0; j < F4L; ++j) xf[j] = ldcs_f4(x4 + lane + 32 * j);

    // 3) top-2 (jax.lax.top_k semantics: ties -> lower index)
    const int k0 = fkey(fv.x), k1 = fkey(fv.y);
    const int k2 = fkey(fv.z), k3 = fkey(fv.w);
    const int c0 = 4 * lane;

    int bk1 = k0, bi1 = c0;
    int bk2 = 0x80000000, bi2 = 0x7fffffff;
    if (k1 > bk1) { bk2 = bk1; bi2 = bi1; bk1 = k1; bi1 = c0 + 1; }
    else if (k1 > bk2) { bk2 = k1; bi2 = c0 + 1; }
    if (k2 > bk1) { bk2 = bk1; bi2 = bi1; bk1 = k2; bi1 = c0 + 2; }
    else if (k2 > bk2) { bk2 = k2; bi2 = c0 + 2; }
    if (k3 > bk1) { bk2 = bk1; bi2 = bi1; bk1 = k3; bi1 = c0 + 3; }
    else if (k3 > bk2) { bk2 = k3; bi2 = c0 + 3; }

    const int K1 = __reduce_max_sync(0xffffffffu, bk1);
    const int I1 = __reduce_min_sync(0xffffffffu, (bk1 == K1) ? bi1 : 0x7fffffff);
    const bool won = (bi1 == I1);
    const int sk = won ? bk2 : bk1;
    const int si = won ? bi2 : bi1;
    const int K2 = __reduce_max_sync(0xffffffffu, sk);
    const int I2 = __reduce_min_sync(0xffffffffu, (sk == K2) ? si : 0x7fffffff);

    const int a = min(I1, I2);
    const int b = max(I1, I2);
    const int pair = b * (b - 1) / 2 + a;

    // 4) both weight rows streamed in one fused loop (L2-resident table)
    const float4* w4 = (const float4*)(weights + (size_t)pair * 2 * DDIM);
    float xss = 0.f, d0 = 0.f, s0 = 0.f, d1 = 0.f, s1 = 0.f;
    #pragma unroll
    for (int j = 0; j < F4L; ++j) {
        const int idx = lane + 32 * j;
        float4 w0 = __ldg(w4 + idx);
        float4 w1 = __ldg(w4 + 192 + idx);
        float4 v  = xf[j];
        xss = fmaf(v.x, v.x, fmaf(v.y, v.y, fmaf(v.z, v.z, fmaf(v.w, v.w, xss))));
        d0  = fmaf(w0.x, v.x, fmaf(w0.y, v.y, fmaf(w0.z, v.z, fmaf(w0.w, v.w, d0))));
        s0  = fmaf(w0.x, w0.x, fmaf(w0.y, w0.y, fmaf(w0.z, w0.z, fmaf(w0.w, w0.w, s0))));
        d1  = fmaf(w1.x, v.x, fmaf(w1.y, v.y, fmaf(w1.z, v.z, fmaf(w1.w, v.w, d1))));
        s1  = fmaf(w1.x, w1.x, fmaf(w1.y, w1.y, fmaf(w1.z, w1.z, fmaf(w1.w, w1.w, s1))));
    }

    xss = warp_sum(xss);
    d0  = warp_sum(d0);
    s0  = warp_sum(s0);
    d1  = warp_sum(d1);
    s1  = warp_sum(s1);

    if (lane == 0) {
        const float sg   = __ldg(sigma + pair);
        const float xinv = 1.0f / fmaxf(sqrtf(xss), 1e-12f);
        const float l0 = sg * d0 * xinv / fmaxf(sqrtf(s0), 1e-12f);
        const float l1 = sg * d1 * xinv / fmaxf(sqrtf(s1), 1e-12f);
        out[row] = (float)((l1 > l0) ? b : a);       // argmax, first on tie
        *(float2*)(out + (size_t)NROWS + 2 * (size_t)row) = make_float2(l0, l1);
    }
}

extern "C" void kernel_launch(void* const* d_in, const int* in_sizes, int n_in,
                              void* d_out, int out_size) {
    const float* x        = (const float*)d_in[0];
    const float* first_o  = (const float*)d_in[1];
    const float* weights  = (const float*)d_in[2];
    const float* sigma    = (const float*)d_in[3];
    float* out = (float*)d_out;

    mlcl_fused<<<NROWS / 8, 256>>>(x, first_o, weights, sigma, out);
}